// round 2
// baseline (speedup 1.0000x reference)
#include <cuda_runtime.h>
#include <math.h>

#define NB 8
#define T  2048
#define E  1024
#define MT (NB*T)   // 16384 rows

// ---- scratch (device globals: allocation-free) ----
__device__ float g_Q[(size_t)MT*E];           // 64 MB
__device__ float g_K[(size_t)MT*E];           // 64 MB
__device__ float g_V[(size_t)MT*E];           // 64 MB
__device__ float g_S[(size_t)NB*T*T];         // 134 MB
__device__ float g_M [NB*T];
__device__ float g_Li[NB*T];

#define BM 128
#define BN 128
#define BK 16

// ============================================================
// Kernel 1: projection  Y = X @ W^T + bias   (NT gemm)
// X: [MT, E] row-major, W: [E(out), E(in)] row-major (K contiguous)
// which: 0->g_K, 1->g_Q, 2->g_V
// ============================================================
__global__ void __launch_bounds__(256) proj_kernel(
    const float* __restrict__ X, const float* __restrict__ W,
    const float* __restrict__ bias, int which)
{
    float* C = (which == 0) ? g_K : (which == 1) ? g_Q : g_V;
    __shared__ __align__(16) float As[BK][BM+4];
    __shared__ __align__(16) float Bs[BK][BN+4];
    const int tid = threadIdx.x;
    const int m0 = blockIdx.y * BM, n0 = blockIdx.x * BN;
    const int tx = tid & 15, ty = tid >> 4;
    const int ar = tid >> 2, ac = (tid & 3) << 2;

    float acc[8][8];
    #pragma unroll
    for (int i = 0; i < 8; i++)
        #pragma unroll
        for (int j = 0; j < 8; j++) acc[i][j] = 0.f;

    for (int k0 = 0; k0 < E; k0 += BK) {
        #pragma unroll
        for (int p = 0; p < 2; ++p) {
            int row = ar + p*64;
            float4 va = *(const float4*)(X + (size_t)(m0+row)*E + k0 + ac);
            As[ac+0][row]=va.x; As[ac+1][row]=va.y; As[ac+2][row]=va.z; As[ac+3][row]=va.w;
            float4 vb = *(const float4*)(W + (size_t)(n0+row)*E + k0 + ac);
            Bs[ac+0][row]=vb.x; Bs[ac+1][row]=vb.y; Bs[ac+2][row]=vb.z; Bs[ac+3][row]=vb.w;
        }
        __syncthreads();
        #pragma unroll
        for (int kk = 0; kk < BK; ++kk) {
            float a[8], bb[8];
            *(float4*)&a[0]  = *(const float4*)&As[kk][ty*8];
            *(float4*)&a[4]  = *(const float4*)&As[kk][ty*8+4];
            *(float4*)&bb[0] = *(const float4*)&Bs[kk][tx*8];
            *(float4*)&bb[4] = *(const float4*)&Bs[kk][tx*8+4];
            #pragma unroll
            for (int i = 0; i < 8; i++)
                #pragma unroll
                for (int j = 0; j < 8; j++) acc[i][j] = fmaf(a[i], bb[j], acc[i][j]);
        }
        __syncthreads();
    }
    #pragma unroll
    for (int i = 0; i < 8; i++) {
        int m = m0 + ty*8 + i;
        #pragma unroll
        for (int j = 0; j < 8; j += 4) {
            int n = n0 + tx*8 + j;
            float4 r;
            r.x = acc[i][j]   + bias[n];
            r.y = acc[i][j+1] + bias[n+1];
            r.z = acc[i][j+2] + bias[n+2];
            r.w = acc[i][j+3] + bias[n+3];
            *(float4*)(C + (size_t)m*E + n) = r;
        }
    }
}

// ============================================================
// Kernel 2: scores S[b,i,j] = Q[b,i,:] . K[b,j,:]  (NT gemm, triangle only)
// Upper-triangle tiles are skipped entirely (never read later).
// ============================================================
__global__ void __launch_bounds__(256) scores_kernel()
{
    if (blockIdx.x > blockIdx.y) return;   // whole tile is masked (j > i)
    const int b = blockIdx.z;
    const float* Q  = g_Q + (size_t)b*T*E;
    const float* Kp = g_K + (size_t)b*T*E;
    float*       S  = g_S + (size_t)b*T*T;

    __shared__ __align__(16) float As[BK][BM+4];
    __shared__ __align__(16) float Bs[BK][BN+4];
    const int tid = threadIdx.x;
    const int m0 = blockIdx.y * BM, n0 = blockIdx.x * BN;
    const int tx = tid & 15, ty = tid >> 4;
    const int ar = tid >> 2, ac = (tid & 3) << 2;

    float acc[8][8];
    #pragma unroll
    for (int i = 0; i < 8; i++)
        #pragma unroll
        for (int j = 0; j < 8; j++) acc[i][j] = 0.f;

    for (int k0 = 0; k0 < E; k0 += BK) {
        #pragma unroll
        for (int p = 0; p < 2; ++p) {
            int row = ar + p*64;
            float4 va = *(const float4*)(Q  + (size_t)(m0+row)*E + k0 + ac);
            As[ac+0][row]=va.x; As[ac+1][row]=va.y; As[ac+2][row]=va.z; As[ac+3][row]=va.w;
            float4 vb = *(const float4*)(Kp + (size_t)(n0+row)*E + k0 + ac);
            Bs[ac+0][row]=vb.x; Bs[ac+1][row]=vb.y; Bs[ac+2][row]=vb.z; Bs[ac+3][row]=vb.w;
        }
        __syncthreads();
        #pragma unroll
        for (int kk = 0; kk < BK; ++kk) {
            float a[8], bb[8];
            *(float4*)&a[0]  = *(const float4*)&As[kk][ty*8];
            *(float4*)&a[4]  = *(const float4*)&As[kk][ty*8+4];
            *(float4*)&bb[0] = *(const float4*)&Bs[kk][tx*8];
            *(float4*)&bb[4] = *(const float4*)&Bs[kk][tx*8+4];
            #pragma unroll
            for (int i = 0; i < 8; i++)
                #pragma unroll
                for (int j = 0; j < 8; j++) acc[i][j] = fmaf(a[i], bb[j], acc[i][j]);
        }
        __syncthreads();
    }
    #pragma unroll
    for (int i = 0; i < 8; i++) {
        int m = m0 + ty*8 + i;
        #pragma unroll
        for (int j = 0; j < 8; j += 4) {
            int n = n0 + tx*8 + j;
            *(float4*)(S + (size_t)m*T + n) =
                make_float4(acc[i][j], acc[i][j+1], acc[i][j+2], acc[i][j+3]);
        }
    }
}

// ============================================================
// Kernel 3: per-column (key j) stats over i >= j: max m_j, sumexp -> 1/l_j
// softmax is over the QUERY axis (faithful quirk).
// ============================================================
__global__ void __launch_bounds__(256) colstats_kernel()
{
    const int b = blockIdx.y;
    const int j = blockIdx.x * 256 + threadIdx.x;
    const float* S = g_S + (size_t)b*T*T;
    float m = -INFINITY, l = 0.f;
    for (int i = j; i < T; ++i) {
        float v = S[(size_t)i*T + j];
        if (v <= m) {
            l += expf(v - m);
        } else {
            l = l * expf(m - v) + 1.f;
            m = v;
        }
    }
    g_M [b*T + j] = m;
    g_Li[b*T + j] = 1.f / l;
}

// ============================================================
// Kernel 4: O[b,i,:] = sum_{j<=i} exp(S[i,j]-m_j)*linv_j * V[b,j,:]
// NN gemm; A tile (P) is built from S at load time; k-loop stops at diagonal.
// ============================================================
__global__ void __launch_bounds__(256) out_gemm(float* __restrict__ Out)
{
    const int b = blockIdx.z;
    const float* S  = g_S + (size_t)b*T*T;
    const float* V  = g_V + (size_t)b*T*E;
    const float* Mv = g_M  + b*T;
    const float* Li = g_Li + b*T;
    float*       O  = Out + (size_t)b*T*E;

    __shared__ __align__(16) float As[BK][BM+4];
    __shared__ __align__(16) float Bs[BK][BN+4];
    const int tid = threadIdx.x;
    const int m0 = blockIdx.y * BM, n0 = blockIdx.x * BN;
    const int tx = tid & 15, ty = tid >> 4;
    const int ar = tid >> 2, ac = (tid & 3) << 2;
    const int br = tid >> 5, bc = (tid & 31) << 2;

    float acc[8][8];
    #pragma unroll
    for (int i = 0; i < 8; i++)
        #pragma unroll
        for (int j = 0; j < 8; j++) acc[i][j] = 0.f;

    const int nkt = m0/BK + BM/BK;   // j-tiles up to and including the diagonal
    for (int kt = 0; kt < nkt; ++kt) {
        const int k0 = kt * BK;
        #pragma unroll
        for (int p = 0; p < 2; ++p) {
            int row = ar + p*64;
            int i = m0 + row;
            float4 s4 = *(const float4*)(S + (size_t)i*T + k0 + ac);
            float sv[4] = {s4.x, s4.y, s4.z, s4.w};
            #pragma unroll
            for (int c = 0; c < 4; ++c) {
                int j = k0 + ac + c;
                As[ac+c][row] = (j <= i) ? expf(sv[c] - Mv[j]) * Li[j] : 0.f;
            }
            int r = br + p*8;
            *(float4*)&Bs[r][bc] = *(const float4*)(V + (size_t)(k0+r)*E + n0 + bc);
        }
        __syncthreads();
        #pragma unroll
        for (int kk = 0; kk < BK; ++kk) {
            float a[8], bb[8];
            *(float4*)&a[0]  = *(const float4*)&As[kk][ty*8];
            *(float4*)&a[4]  = *(const float4*)&As[kk][ty*8+4];
            *(float4*)&bb[0] = *(const float4*)&Bs[kk][tx*8];
            *(float4*)&bb[4] = *(const float4*)&Bs[kk][tx*8+4];
            #pragma unroll
            for (int i = 0; i < 8; i++)
                #pragma unroll
                for (int j = 0; j < 8; j++) acc[i][j] = fmaf(a[i], bb[j], acc[i][j]);
        }
        __syncthreads();
    }
    #pragma unroll
    for (int i = 0; i < 8; i++) {
        int m = m0 + ty*8 + i;
        #pragma unroll
        for (int j = 0; j < 8; j += 4) {
            int n = n0 + tx*8 + j;
            *(float4*)(O + (size_t)m*E + n) =
                make_float4(acc[i][j], acc[i][j+1], acc[i][j+2], acc[i][j+3]);
        }
    }
}

// ============================================================
extern "C" void kernel_launch(void* const* d_in, const int* in_sizes, int n_in,
                              void* d_out, int out_size)
{
    const float* x_emb = (const float*)d_in[0];
    // d_in[1] = token ids (unused by reference math)
    const float* Wk = (const float*)d_in[2];
    const float* bk = (const float*)d_in[3];
    const float* Wq = (const float*)d_in[4];
    const float* bq = (const float*)d_in[5];
    const float* Wv = (const float*)d_in[6];
    const float* bv = (const float*)d_in[7];
    float* out = (float*)d_out;

    dim3 blk(256);
    dim3 gproj(E/BN, MT/BM);          // (8, 128)
    proj_kernel<<<gproj, blk>>>(x_emb, Wk, bk, 0);
    proj_kernel<<<gproj, blk>>>(x_emb, Wq, bq, 1);
    proj_kernel<<<gproj, blk>>>(x_emb, Wv, bv, 2);

    dim3 gsc(T/BN, T/BM, NB);         // (16, 16, 8)
    scores_kernel<<<gsc, blk>>>();

    dim3 gcs(T/256, NB);              // (8, 8)
    colstats_kernel<<<gcs, blk>>>();

    dim3 gout(E/BN, T/BM, NB);        // (8, 16, 8)
    out_gemm<<<gout, blk>>>(out);
}